// round 15
// baseline (speedup 1.0000x reference)
#include <cuda_runtime.h>
#include <cuda_bf16.h>
#include <math.h>
#include <stdint.h>

struct Coeffs {
    float s1, s0;            // T = s1*A + s0*I
    float hp;                // G = y0 + hp*T (hp = p/2); V' = G*G
    float qe1, re1, sf1;     // F1 = V' + qe1*G + re1*T + sf1*I
    float qe2, re2, sf2;     // F2 = V' + qe2*G + re2*T + sf2*I
    float dqe, dre;          // F1 = F2 + dqe*G + dre*T (refill path)
    float a8;                // p(T) = a8*(F1*F2) + kg12*G + kt13*T + k14*I
    float kg12, kt13, k14;
};

// smem: bf16 hi/lo matrices: T, G, F2.
#define BSTRIDE 72
#define BMATB   (64 * BSTRIDE * 2)        // 9216
#define SM_T_HI  0
#define SM_T_LO  (1 * BMATB)
#define SM_G_HI  (2 * BMATB)
#define SM_G_LO  (3 * BMATB)
#define SM_F_HI  (4 * BMATB)
#define SM_F_LO  (5 * BMATB)
#define SMEM_BYTES (6 * BMATB)            // 55296

__device__ __forceinline__ uint32_t smem_u32(const void* p) {
    uint32_t r;
    asm("{ .reg .u64 t; cvta.to.shared.u64 t, %1; cvt.u32.u64 %0, t; }" : "=r"(r) : "l"(p));
    return r;
}
__device__ __forceinline__ void ldsm_x4(uint32_t addr, uint32_t* r) {
    asm volatile("ldmatrix.sync.aligned.m8n8.x4.shared.b16 {%0,%1,%2,%3}, [%4];"
        : "=r"(r[0]), "=r"(r[1]), "=r"(r[2]), "=r"(r[3]) : "r"(addr));
}
__device__ __forceinline__ void ldsm_x4_t(uint32_t addr, uint32_t* r) {
    asm volatile("ldmatrix.sync.aligned.m8n8.x4.trans.shared.b16 {%0,%1,%2,%3}, [%4];"
        : "=r"(r[0]), "=r"(r[1]), "=r"(r[2]), "=r"(r[3]) : "r"(addr));
}
__device__ __forceinline__ void stsm_x4(uint32_t addr, const uint32_t* r) {
    asm volatile("stmatrix.sync.aligned.m8n8.x4.shared.b16 [%0], {%1,%2,%3,%4};"
        :: "r"(addr), "r"(r[0]), "r"(r[1]), "r"(r[2]), "r"(r[3]) : "memory");
}
__device__ __forceinline__ void stsm_x4_t(uint32_t addr, const uint32_t* r) {
    asm volatile("stmatrix.sync.aligned.m8n8.x4.trans.shared.b16 [%0], {%1,%2,%3,%4};"
        :: "r"(addr), "r"(r[0]), "r"(r[1]), "r"(r[2]), "r"(r[3]) : "memory");
}
__device__ __forceinline__ void mma_bf16(float* c, const uint32_t* a, const uint32_t* b) {
    asm volatile("mma.sync.aligned.m16n8k16.row.col.f32.bf16.bf16.f32 "
        "{%0,%1,%2,%3}, {%4,%5,%6,%7}, {%8,%9}, {%0,%1,%2,%3};"
        : "+f"(c[0]), "+f"(c[1]), "+f"(c[2]), "+f"(c[3])
        : "r"(a[0]), "r"(a[1]), "r"(a[2]), "r"(a[3]), "r"(b[0]), "r"(b[1]));
}
__device__ __forceinline__ float loW(uint32_t w) { return __uint_as_float(w << 16); }
__device__ __forceinline__ float hiW(uint32_t w) { return __uint_as_float(w & 0xFFFF0000u); }

// fast split: packed cvt for hi pair, exact residual, packed cvt for lo pair
__device__ __forceinline__ void split2(float x0, float x1, uint32_t& hw, uint32_t& lw) {
    asm("cvt.rn.bf16x2.f32 %0, %1, %2;" : "=r"(hw) : "f"(x1), "f"(x0));
    const float l0 = x0 - loW(hw);
    const float l1 = x1 - hiW(hw);
    asm("cvt.rn.bf16x2.f32 %0, %1, %2;" : "=r"(lw) : "f"(l1), "f"(l0));
}

#define SMW(buf, i, j) (*reinterpret_cast<const uint32_t*>(smem + (buf) + ((i) * BSTRIDE + (j)) * 2))

// Rotated matmul: C tile 2*dp+sub holds actual columns 16*((w+dp)&3)+8*sub.
// Ah[dpk] holds A-fragment for k-chunk (w+dpk)&3.
// diag=true (B == A, symmetric): dp==0 uses own A regs permuted (compile-time).
// tri=true: skip chunks with w+dp >= 4 (strictly-lower output blocks), warp-uniform.
__device__ __forceinline__ void mm64_rot(const uint32_t sb, const int b_hi, const int b_lo,
                                         const uint32_t Ah[4][4], const uint32_t Al[4][4],
                                         const int lane, const int w, float C[8][4],
                                         const bool diag, const bool tri)
{
    #pragma unroll
    for (int t = 0; t < 8; ++t)
        #pragma unroll
        for (int r = 0; r < 4; ++r) C[t][r] = 0.0f;

    const int lrow = lane & 15;
    const int lcol8 = 8 * (lane >> 4);

    #pragma unroll
    for (int dpk = 0; dpk < 4; ++dpk) {
        const int kca = (w + dpk) & 3;
        const uint32_t rowoff = (uint32_t)(((16 * kca + lrow) * BSTRIDE + lcol8) * 2);
        #pragma unroll
        for (int dp = 0; dp < 4; ++dp) {
            if (tri && (w + dp >= 4)) continue;     // warp-uniform runtime guard
            uint32_t bh[4], bl[4];
            if (diag && dp == 0) {                  // compile-time branch
                bh[0] = Ah[dpk][0]; bh[1] = Ah[dpk][2]; bh[2] = Ah[dpk][1]; bh[3] = Ah[dpk][3];
                bl[0] = Al[dpk][0]; bl[1] = Al[dpk][2]; bl[2] = Al[dpk][1]; bl[3] = Al[dpk][3];
            } else {
                const int ppa = (w + dp) & 3;
                const uint32_t b_off = rowoff + (uint32_t)(32 * ppa);
                ldsm_x4_t(sb + b_hi + b_off, bh);
                ldsm_x4_t(sb + b_lo + b_off, bl);
            }
            mma_bf16(C[2 * dp],     Ah[dpk], bh);
            mma_bf16(C[2 * dp + 1], Ah[dpk], bh + 2);
            mma_bf16(C[2 * dp],     Ah[dpk], bl);
            mma_bf16(C[2 * dp + 1], Ah[dpk], bl + 2);
            mma_bf16(C[2 * dp],     Al[dpk], bh);
            mma_bf16(C[2 * dp + 1], Al[dpk], bh + 2);
        }
    }
}

__global__ void __launch_bounds__(128, 4)
logeig_s8u_kernel(const float* __restrict__ in, float* __restrict__ out, const Coeffs cc)
{
    extern __shared__ __align__(16) char smem[];
    const uint32_t sb = smem_u32(smem);
    const int tid = threadIdx.x;
    const int w = tid >> 5, lane = tid & 31;
    const int grp = lane >> 2, tid4 = lane & 3;
    const int ib = 16 * w + grp;
    const int jb = 2 * tid4;
    const size_t mat = blockIdx.x;

    // stmatrix lane-address components
    const int mrow8 = lane & 7;
    const int msel  = (lane >> 3) & 1;
    const int mhi   = lane >> 4;

    // ---- build T = s1*A + s0*I as bf16 hi/lo in smem ----
    {
        const float* Ag = in + mat * 4096 + (size_t)(tid >> 1) * 64 + (tid & 1) * 32;
        char* hrow = smem + SM_T_HI + ((tid >> 1) * BSTRIDE + (tid & 1) * 32) * 2;
        char* lrow = smem + SM_T_LO + ((tid >> 1) * BSTRIDE + (tid & 1) * 32) * 2;
        const int di = (tid >> 1) - (tid & 1) * 32;
        #pragma unroll
        for (int q = 0; q < 8; ++q) {
            const float4 v = *reinterpret_cast<const float4*>(Ag + q * 4);
            float t0 = cc.s1 * v.x, t1 = cc.s1 * v.y, t2 = cc.s1 * v.z, t3 = cc.s1 * v.w;
            if (di == q * 4 + 0) t0 += cc.s0;
            if (di == q * 4 + 1) t1 += cc.s0;
            if (di == q * 4 + 2) t2 += cc.s0;
            if (di == q * 4 + 3) t3 += cc.s0;
            uint32_t h0, l0, h1, l1;
            split2(t0, t1, h0, l0);
            split2(t2, t3, h1, l1);
            reinterpret_cast<uint32_t*>(hrow)[2 * q] = h0;
            reinterpret_cast<uint32_t*>(hrow)[2 * q + 1] = h1;
            reinterpret_cast<uint32_t*>(lrow)[2 * q] = l0;
            reinterpret_cast<uint32_t*>(lrow)[2 * q + 1] = l1;
        }
    }
    __syncthreads();

    // ---- A-fragments of T, rotated: Ah[dp] = k-chunk (w+dp)&3 ----
    uint32_t Ah[4][4], Al[4][4];
    {
        const int lrow = lane & 15;
        const int lcol8 = 8 * (lane >> 4);
        #pragma unroll
        for (int dp = 0; dp < 4; ++dp) {
            const int kca = (w + dp) & 3;
            const uint32_t a_off = (uint32_t)(((16 * w + lrow) * BSTRIDE + 16 * kca + lcol8) * 2);
            ldsm_x4(sb + SM_T_HI + a_off, Ah[dp]);
            ldsm_x4(sb + SM_T_LO + a_off, Al[dp]);
        }
    }

    float C[8][4];

    // ---- M1: C = T*T = y0 (tri + diag); G = y0 + hp*T -> regs + stmatrix (upper + mirror) ----
    mm64_rot(sb, SM_T_HI, SM_T_LO, Ah, Al, lane, w, C, true, true);
    #pragma unroll
    for (int dp = 0; dp < 4; ++dp) {
        if (w + dp >= 4) continue;                   // tile not computed
        const int jblk = 16 * (w + dp);              // no wrap under tri
        #pragma unroll
        for (int q = 0; q < 4; ++q) {
            const uint32_t th = Ah[dp][q], tl = Al[dp][q];
            const int t = 2 * dp + (q >> 1), rr = q & 1;
            const float x0 = C[t][2 * rr]     + cc.hp * (loW(th) + loW(tl));
            const float x1 = C[t][2 * rr + 1] + cc.hp * (hiW(th) + hiW(tl));
            split2(x0, x1, Ah[dp][q], Al[dp][q]);
        }
        const uint32_t naddr = (uint32_t)(((16 * w + 8 * msel + mrow8) * BSTRIDE + jblk + 8 * mhi) * 2);
        stsm_x4(sb + SM_G_HI + naddr, Ah[dp]);
        stsm_x4(sb + SM_G_LO + naddr, Al[dp]);
        if (dp > 0) {
            const uint32_t maddr = (uint32_t)(((jblk + 8 * mhi + mrow8) * BSTRIDE + 16 * w + 8 * msel) * 2);
            stsm_x4_t(sb + SM_G_HI + maddr, Ah[dp]);
            stsm_x4_t(sb + SM_G_LO + maddr, Al[dp]);
        }
    }
    __syncthreads();   // G (full, mirrored) visible

    // ---- refill A-fragments of G for skipped chunks (kca < w) ----
    {
        const int lrow = lane & 15;
        const int lcol8 = 8 * (lane >> 4);
        #pragma unroll
        for (int dp = 0; dp < 4; ++dp) {
            if (w + dp < 4) continue;                // computed above
            const int kca = w + dp - 4;
            const uint32_t a_off = (uint32_t)(((16 * w + lrow) * BSTRIDE + 16 * kca + lcol8) * 2);
            ldsm_x4(sb + SM_G_HI + a_off, Ah[dp]);
            ldsm_x4(sb + SM_G_LO + a_off, Al[dp]);
        }
    }

    // ---- M2: C = G*G = V' (tri + diag); F1 -> A regs (upper), F2 -> stmatrix (upper + mirror) ----
    mm64_rot(sb, SM_G_HI, SM_G_LO, Ah, Al, lane, w, C, true, true);
    #pragma unroll
    for (int dp = 0; dp < 4; ++dp) {
        if (w + dp >= 4) continue;                   // tile not computed
        const int jblk = 16 * (w + dp);
        uint32_t f2h[4], f2l[4];
        #pragma unroll
        for (int q = 0; q < 4; ++q) {
            const int t = 2 * dp + (q >> 1), rr = q & 1;
            const int i = ib + 8 * rr;
            const int j0 = jblk + 8 * (q >> 1) + jb;
            const uint32_t th = SMW(SM_T_HI, i, j0), tl = SMW(SM_T_LO, i, j0);
            const uint32_t gh = Ah[dp][q], gl = Al[dp][q];
            const float T0 = loW(th) + loW(tl), T1 = hiW(th) + hiW(tl);
            const float G0 = loW(gh) + loW(gl), G1 = hiW(gh) + hiW(gl);
            float f10 = C[t][2 * rr]     + cc.qe1 * G0 + cc.re1 * T0;
            float f11 = C[t][2 * rr + 1] + cc.qe1 * G1 + cc.re1 * T1;
            float f20 = C[t][2 * rr]     + cc.qe2 * G0 + cc.re2 * T0;
            float f21 = C[t][2 * rr + 1] + cc.qe2 * G1 + cc.re2 * T1;
            if (i == j0)     { f10 += cc.sf1; f20 += cc.sf2; }
            if (i == j0 + 1) { f11 += cc.sf1; f21 += cc.sf2; }
            split2(f10, f11, Ah[dp][q], Al[dp][q]);
            split2(f20, f21, f2h[q], f2l[q]);
        }
        const uint32_t naddr = (uint32_t)(((16 * w + 8 * msel + mrow8) * BSTRIDE + jblk + 8 * mhi) * 2);
        stsm_x4(sb + SM_F_HI + naddr, f2h);
        stsm_x4(sb + SM_F_LO + naddr, f2l);
        if (dp > 0) {
            const uint32_t maddr = (uint32_t)(((jblk + 8 * mhi + mrow8) * BSTRIDE + 16 * w + 8 * msel) * 2);
            stsm_x4_t(sb + SM_F_HI + maddr, f2h);
            stsm_x4_t(sb + SM_F_LO + maddr, f2l);
        }
    }
    __syncthreads();   // F2 (full, mirrored) visible

    // ---- refill A-fragments of F1 for skipped chunks: F1 = F2 + dqe*G + dre*T ----
    {
        const int lrow = lane & 15;
        const int lcol8 = 8 * (lane >> 4);
        #pragma unroll
        for (int dp = 0; dp < 4; ++dp) {
            if (w + dp < 4) continue;                // computed above
            const int kca = w + dp - 4;
            const uint32_t a_off = (uint32_t)(((16 * w + lrow) * BSTRIDE + 16 * kca + lcol8) * 2);
            uint32_t fh[4], fl[4], gh[4], gl[4], th[4], tl[4];
            ldsm_x4(sb + SM_F_HI + a_off, fh);
            ldsm_x4(sb + SM_F_LO + a_off, fl);
            ldsm_x4(sb + SM_G_HI + a_off, gh);
            ldsm_x4(sb + SM_G_LO + a_off, gl);
            ldsm_x4(sb + SM_T_HI + a_off, th);
            ldsm_x4(sb + SM_T_LO + a_off, tl);
            #pragma unroll
            for (int q = 0; q < 4; ++q) {
                const float x0 = (loW(fh[q]) + loW(fl[q])) + cc.dqe * (loW(gh[q]) + loW(gl[q]))
                               + cc.dre * (loW(th[q]) + loW(tl[q]));
                const float x1 = (hiW(fh[q]) + hiW(fl[q])) + cc.dqe * (hiW(gh[q]) + hiW(gl[q]))
                               + cc.dre * (hiW(th[q]) + hiW(tl[q]));
                split2(x0, x1, Ah[dp][q], Al[dp][q]);
            }
        }
    }

    // ---- M3: C = F1*F2 (triangle-restricted; F1 != F2 so no diag trick) ----
    mm64_rot(sb, SM_F_HI, SM_F_LO, Ah, Al, lane, w, C, false, true);

    // ---- final combo + epilogue: p(T) = a8*C + kg12*G + kt13*T + k14*I ----
    {
        const float SQ2 = 1.41421356237309515f;
        float* ob = out + mat * 2080;
        #pragma unroll
        for (int t = 0; t < 8; ++t) {
            const int dp = t >> 1;
            if (dp > 0 && w + dp >= 4) continue;   // tile not computed (below diagonal)
            const int j0 = 16 * ((w + dp) & 3) + 8 * (t & 1) + jb;
            #pragma unroll
            for (int rr = 0; rr < 2; ++rr) {
                const int i = ib + 8 * rr;
                const uint32_t th = SMW(SM_T_HI, i, j0), tl = SMW(SM_T_LO, i, j0);
                const uint32_t gh = SMW(SM_G_HI, i, j0), gl = SMW(SM_G_LO, i, j0);
                float f0 = cc.a8 * C[t][2 * rr]     + cc.kg12 * (loW(gh) + loW(gl))
                         + cc.kt13 * (loW(th) + loW(tl));
                float f1 = cc.a8 * C[t][2 * rr + 1] + cc.kg12 * (hiW(gh) + hiW(gl))
                         + cc.kt13 * (hiW(th) + hiW(tl));
                if (i == j0)     f0 += cc.k14;
                if (i == j0 + 1) f1 += cc.k14;
                const int rowbase = i * (129 - i) / 2 - i;
                if (j0 >= i)     ob[rowbase + j0]     = (i == j0)     ? fabsf(f0) : fabsf(f0) * SQ2;
                if (j0 + 1 >= i) ob[rowbase + j0 + 1] = (i == j0 + 1) ? fabsf(f1) : fabsf(f1) * SQ2;
            }
        }
    }
}

extern "C" void kernel_launch(void* const* d_in, const int* in_sizes, int n_in,
                              void* d_out, int out_size)
{
    const float* in = (const float*)d_in[0];
    float* out = (float*)d_out;
    const int nmat = in_sizes[0] / 4096;

    // Chebyshev series of log on [a,b], truncated at degree 8 -> monomials in t.
    const double a = 0.97, b = 7.0;
    const double mm = 0.5 * (a + b);
    const double wdl = (b - a) / (b + a);
    const double z = (sqrt(1.0 - wdl * wdl) - 1.0) / wdl;

    const int ND = 8;
    double c[ND + 1];
    c[0] = log(mm) - log(1.0 + z * z);
    double zk = 1.0;
    for (int k = 1; k <= ND; ++k) { zk *= z; c[k] = -2.0 * zk / (double)k; }

    double am[ND + 1];
    for (int j = 0; j <= ND; ++j) am[j] = 0.0;
    {
        double Tm1[ND + 1] = {0}, Tk[ND + 1] = {0}, Tn[ND + 1];
        Tm1[0] = 1.0;
        Tk[1] = 1.0;
        am[0] += c[0] * Tm1[0];
        am[1] += c[1] * Tk[1];
        for (int k = 2; k <= ND; ++k) {
            for (int j = 0; j <= ND; ++j) Tn[j] = -Tm1[j];
            for (int j = 1; j <= ND; ++j) Tn[j] += 2.0 * Tk[j - 1];
            for (int j = 0; j <= ND; ++j) { am[j] += c[k] * Tn[j]; Tm1[j] = Tk[j]; Tk[j] = Tn[j]; }
        }
    }

    // 3-product scheme coefficients (closed form).
    const double a8 = am[8];
    double bb[8];
    for (int k = 0; k < 8; ++k) bb[k] = am[k] / a8;

    const double p  = bb[7] / 2.0;
    const double Q  = bb[6] - p * p;
    const double R  = bb[5] - p * Q;
    const double dq = 1.0;
    const double S  = bb[4] - p * R - Q * Q / 4.0 + dq * dq;
    const double dr = (p * S + Q * R / 2.0 - bb[3]) / (2.0 * dq);
    const double q1 = Q / 2.0 + dq, q2 = Q / 2.0 - dq;
    const double r1 = R / 2.0 + dr, r2 = R / 2.0 - dr;
    const double s1 = S / 2.0,      s2 = S / 2.0;
    const double c12 = bb[2] - Q * S / 2.0 - R * R / 4.0 + dr * dr;
    const double c13 = bb[1] - R * S / 2.0;
    const double c14 = bb[0] - S * S / 4.0;

    // Square-form refactor: G = y0 + (p/2)T; V = G^2 - (p^2/4)y0; y0 = G - (p/2)T.
    const double hp  = p / 2.0;
    const double qe1 = q1 - p * p / 4.0;
    const double qe2 = q2 - p * p / 4.0;
    const double re1 = r1 - hp * qe1;
    const double re2 = r2 - hp * qe2;
    const double kg12 = a8 * c12;
    const double kt13 = a8 * c13 - hp * kg12;

    Coeffs cc;
    cc.s1 = (float)(2.0 / (b - a));
    cc.s0 = (float)(-(a + b) / (b - a));
    cc.hp = (float)hp;
    cc.qe1 = (float)qe1; cc.re1 = (float)re1; cc.sf1 = (float)s1;
    cc.qe2 = (float)qe2; cc.re2 = (float)re2; cc.sf2 = (float)s2;
    cc.dqe = (float)(qe1 - qe2);
    cc.dre = (float)(re1 - re2);
    cc.a8 = (float)a8;
    cc.kg12 = (float)kg12;
    cc.kt13 = (float)kt13;
    cc.k14  = (float)(a8 * c14);

    cudaFuncSetAttribute(logeig_s8u_kernel,
                         cudaFuncAttributeMaxDynamicSharedMemorySize, SMEM_BYTES);
    logeig_s8u_kernel<<<nmat, 128, SMEM_BYTES>>>(in, out, cc);
}

// round 16
// speedup vs baseline: 1.0831x; 1.0831x over previous
#include <cuda_runtime.h>
#include <cuda_bf16.h>
#include <math.h>
#include <stdint.h>

struct Coeffs {
    float s1, s0;            // T = s1*A + s0*I
    float hp;                // G = y0 + hp*T (hp = p/2); V' = G*G
    float qe1, re1, sf1;     // F1 = V' + qe1*G + re1*T + sf1*I
    float qe2, re2, sf2;     // F2 = V' + qe2*G + re2*T + sf2*I
    float a8;                // p(T) = a8*(F1*F2) + kg12*G + kt13*T + k14*I
    float kg12, kt13, k14;
};

// smem: bf16 hi/lo matrices: T, G, F2.
#define BSTRIDE 72
#define BMATB   (64 * BSTRIDE * 2)        // 9216
#define SM_T_HI  0
#define SM_T_LO  (1 * BMATB)
#define SM_G_HI  (2 * BMATB)
#define SM_G_LO  (3 * BMATB)
#define SM_F_HI  (4 * BMATB)
#define SM_F_LO  (5 * BMATB)
#define SMEM_BYTES (6 * BMATB)            // 55296

__device__ __forceinline__ uint32_t smem_u32(const void* p) {
    uint32_t r;
    asm("{ .reg .u64 t; cvta.to.shared.u64 t, %1; cvt.u32.u64 %0, t; }" : "=r"(r) : "l"(p));
    return r;
}
__device__ __forceinline__ void ldsm_x4(uint32_t addr, uint32_t* r) {
    asm volatile("ldmatrix.sync.aligned.m8n8.x4.shared.b16 {%0,%1,%2,%3}, [%4];"
        : "=r"(r[0]), "=r"(r[1]), "=r"(r[2]), "=r"(r[3]) : "r"(addr));
}
__device__ __forceinline__ void ldsm_x4_t(uint32_t addr, uint32_t* r) {
    asm volatile("ldmatrix.sync.aligned.m8n8.x4.trans.shared.b16 {%0,%1,%2,%3}, [%4];"
        : "=r"(r[0]), "=r"(r[1]), "=r"(r[2]), "=r"(r[3]) : "r"(addr));
}
__device__ __forceinline__ void stsm_x4(uint32_t addr, const uint32_t* r) {
    asm volatile("stmatrix.sync.aligned.m8n8.x4.shared.b16 [%0], {%1,%2,%3,%4};"
        :: "r"(addr), "r"(r[0]), "r"(r[1]), "r"(r[2]), "r"(r[3]) : "memory");
}
__device__ __forceinline__ void stsm_x4_t(uint32_t addr, const uint32_t* r) {
    asm volatile("stmatrix.sync.aligned.m8n8.x4.trans.shared.b16 [%0], {%1,%2,%3,%4};"
        :: "r"(addr), "r"(r[0]), "r"(r[1]), "r"(r[2]), "r"(r[3]) : "memory");
}
__device__ __forceinline__ void mma_bf16(float* c, const uint32_t* a, const uint32_t* b) {
    asm volatile("mma.sync.aligned.m16n8k16.row.col.f32.bf16.bf16.f32 "
        "{%0,%1,%2,%3}, {%4,%5,%6,%7}, {%8,%9}, {%0,%1,%2,%3};"
        : "+f"(c[0]), "+f"(c[1]), "+f"(c[2]), "+f"(c[3])
        : "r"(a[0]), "r"(a[1]), "r"(a[2]), "r"(a[3]), "r"(b[0]), "r"(b[1]));
}
__device__ __forceinline__ float loW(uint32_t w) { return __uint_as_float(w << 16); }
__device__ __forceinline__ float hiW(uint32_t w) { return __uint_as_float(w & 0xFFFF0000u); }

// fast split: packed cvt for hi pair, exact residual, packed cvt for lo pair
__device__ __forceinline__ void split2(float x0, float x1, uint32_t& hw, uint32_t& lw) {
    asm("cvt.rn.bf16x2.f32 %0, %1, %2;" : "=r"(hw) : "f"(x1), "f"(x0));
    const float l0 = x0 - loW(hw);
    const float l1 = x1 - hiW(hw);
    asm("cvt.rn.bf16x2.f32 %0, %1, %2;" : "=r"(lw) : "f"(l1), "f"(l0));
}

#define SMW(buf, i, j) (*reinterpret_cast<const uint32_t*>(smem + (buf) + ((i) * BSTRIDE + (j)) * 2))

// Rotated matmul: C tile 2*dp+sub holds actual columns 16*((w+dp)&3)+8*sub.
// Ah[dpk] holds A-fragment for k-chunk (w+dpk)&3.
// diag=true (B == A, symmetric): dp==0 uses own A regs permuted (compile-time).
// ntile: number of dp column-chunks to compute (warp-uniform; 4 = full).
__device__ __forceinline__ void mm64_rot(const uint32_t sb, const int b_hi, const int b_lo,
                                         const uint32_t Ah[4][4], const uint32_t Al[4][4],
                                         const int lane, const int w, float C[8][4],
                                         const bool diag, const int ntile)
{
    #pragma unroll
    for (int t = 0; t < 8; ++t)
        #pragma unroll
        for (int r = 0; r < 4; ++r) C[t][r] = 0.0f;

    const int lrow = lane & 15;
    const int lcol8 = 8 * (lane >> 4);

    #pragma unroll
    for (int dpk = 0; dpk < 4; ++dpk) {
        const int kca = (w + dpk) & 3;
        const uint32_t rowoff = (uint32_t)(((16 * kca + lrow) * BSTRIDE + lcol8) * 2);
        #pragma unroll
        for (int dp = 0; dp < 4; ++dp) {
            if (dp >= ntile) continue;              // warp-uniform runtime guard
            uint32_t bh[4], bl[4];
            if (diag && dp == 0) {                  // compile-time branch
                bh[0] = Ah[dpk][0]; bh[1] = Ah[dpk][2]; bh[2] = Ah[dpk][1]; bh[3] = Ah[dpk][3];
                bl[0] = Al[dpk][0]; bl[1] = Al[dpk][2]; bl[2] = Al[dpk][1]; bl[3] = Al[dpk][3];
            } else {
                const int ppa = (w + dp) & 3;
                const uint32_t b_off = rowoff + (uint32_t)(32 * ppa);
                ldsm_x4_t(sb + b_hi + b_off, bh);
                ldsm_x4_t(sb + b_lo + b_off, bl);
            }
            mma_bf16(C[2 * dp],     Ah[dpk], bh);
            mma_bf16(C[2 * dp + 1], Ah[dpk], bh + 2);
            mma_bf16(C[2 * dp],     Ah[dpk], bl);
            mma_bf16(C[2 * dp + 1], Ah[dpk], bl + 2);
            mma_bf16(C[2 * dp],     Al[dpk], bh);
            mma_bf16(C[2 * dp + 1], Al[dpk], bh + 2);
        }
    }
}

__global__ void __launch_bounds__(128, 4)
logeig_s8b_kernel(const float* __restrict__ in, float* __restrict__ out, const Coeffs cc)
{
    extern __shared__ __align__(16) char smem[];
    const uint32_t sb = smem_u32(smem);
    const int tid = threadIdx.x;
    const int w = tid >> 5, lane = tid & 31;
    const int grp = lane >> 2, tid4 = lane & 3;
    const int ib = 16 * w + grp;
    const int jb = 2 * tid4;
    const size_t mat = blockIdx.x;

    // balanced tile counts per warp: {3,3,2,2}
    const int npc = 3 - (w >> 1);

    // stmatrix lane-address components
    const int mrow8 = lane & 7;
    const int msel  = (lane >> 3) & 1;
    const int mhi   = lane >> 4;

    // ---- build T = s1*A + s0*I as bf16 hi/lo in smem ----
    {
        const float* Ag = in + mat * 4096 + (size_t)(tid >> 1) * 64 + (tid & 1) * 32;
        char* hrow = smem + SM_T_HI + ((tid >> 1) * BSTRIDE + (tid & 1) * 32) * 2;
        char* lrow = smem + SM_T_LO + ((tid >> 1) * BSTRIDE + (tid & 1) * 32) * 2;
        const int di = (tid >> 1) - (tid & 1) * 32;
        #pragma unroll
        for (int q = 0; q < 8; ++q) {
            const float4 v = *reinterpret_cast<const float4*>(Ag + q * 4);
            float t0 = cc.s1 * v.x, t1 = cc.s1 * v.y, t2 = cc.s1 * v.z, t3 = cc.s1 * v.w;
            if (di == q * 4 + 0) t0 += cc.s0;
            if (di == q * 4 + 1) t1 += cc.s0;
            if (di == q * 4 + 2) t2 += cc.s0;
            if (di == q * 4 + 3) t3 += cc.s0;
            uint32_t h0, l0, h1, l1;
            split2(t0, t1, h0, l0);
            split2(t2, t3, h1, l1);
            uint2 hv; hv.x = h0; hv.y = h1;
            uint2 lv; lv.x = l0; lv.y = l1;
            *reinterpret_cast<uint2*>(hrow + q * 8) = hv;
            *reinterpret_cast<uint2*>(lrow + q * 8) = lv;
        }
    }
    __syncthreads();

    // ---- A-fragments of T, rotated: Ah[dp] = k-chunk (w+dp)&3 ----
    uint32_t Ah[4][4], Al[4][4];
    {
        const int lrow = lane & 15;
        const int lcol8 = 8 * (lane >> 4);
        #pragma unroll
        for (int dp = 0; dp < 4; ++dp) {
            const int kca = (w + dp) & 3;
            const uint32_t a_off = (uint32_t)(((16 * w + lrow) * BSTRIDE + 16 * kca + lcol8) * 2);
            ldsm_x4(sb + SM_T_HI + a_off, Ah[dp]);
            ldsm_x4(sb + SM_T_LO + a_off, Al[dp]);
        }
    }

    float C[8][4];

    // ---- M1: C = T*T = y0 (balanced tri + diag); G = y0 + hp*T -> regs + stmatrix ----
    mm64_rot(sb, SM_T_HI, SM_T_LO, Ah, Al, lane, w, C, true, npc);
    #pragma unroll
    for (int dp = 0; dp < 4; ++dp) {
        if (dp >= npc) continue;                     // tile not computed
        const int jblk = 16 * ((w + dp) & 3);        // may wrap (lower tile, mirror-covered)
        #pragma unroll
        for (int q = 0; q < 4; ++q) {
            const uint32_t th = Ah[dp][q], tl = Al[dp][q];
            const int t = 2 * dp + (q >> 1), rr = q & 1;
            const float x0 = C[t][2 * rr]     + cc.hp * (loW(th) + loW(tl));
            const float x1 = C[t][2 * rr + 1] + cc.hp * (hiW(th) + hiW(tl));
            split2(x0, x1, Ah[dp][q], Al[dp][q]);
        }
        const uint32_t naddr = (uint32_t)(((16 * w + 8 * msel + mrow8) * BSTRIDE + jblk + 8 * mhi) * 2);
        stsm_x4(sb + SM_G_HI + naddr, Ah[dp]);
        stsm_x4(sb + SM_G_LO + naddr, Al[dp]);
        if (dp > 0) {
            const uint32_t maddr = (uint32_t)(((jblk + 8 * mhi + mrow8) * BSTRIDE + 16 * w + 8 * msel) * 2);
            stsm_x4_t(sb + SM_G_HI + maddr, Ah[dp]);
            stsm_x4_t(sb + SM_G_LO + maddr, Al[dp]);
        }
    }
    __syncthreads();   // G (full, mirrored) visible

    // ---- refill A-fragments of G for skipped chunks (dp >= npc) ----
    {
        const int lrow = lane & 15;
        const int lcol8 = 8 * (lane >> 4);
        #pragma unroll
        for (int dp = 0; dp < 4; ++dp) {
            if (dp < npc) continue;                  // computed above
            const int kca = (w + dp) & 3;
            const uint32_t a_off = (uint32_t)(((16 * w + lrow) * BSTRIDE + 16 * kca + lcol8) * 2);
            ldsm_x4(sb + SM_G_HI + a_off, Ah[dp]);
            ldsm_x4(sb + SM_G_LO + a_off, Al[dp]);
        }
    }

    // ---- M2: C = G*G = V' (full, diag from regs); F1 -> A regs, F2 -> STS ----
    mm64_rot(sb, SM_G_HI, SM_G_LO, Ah, Al, lane, w, C, true, 4);
    #pragma unroll
    for (int t = 0; t < 8; ++t) {
        const int dp = t >> 1;
        const int j0 = 16 * ((w + dp) & 3) + 8 * (t & 1) + jb;
        #pragma unroll
        for (int rr = 0; rr < 2; ++rr) {
            const int i = ib + 8 * rr;
            const uint32_t th = SMW(SM_T_HI, i, j0), tl = SMW(SM_T_LO, i, j0);
            const uint32_t gh = Ah[dp][2 * (t & 1) + rr], gl = Al[dp][2 * (t & 1) + rr];
            const float T0 = loW(th) + loW(tl), T1 = hiW(th) + hiW(tl);
            const float G0 = loW(gh) + loW(gl), G1 = hiW(gh) + hiW(gl);
            float f10 = C[t][2 * rr]     + cc.qe1 * G0 + cc.re1 * T0;
            float f11 = C[t][2 * rr + 1] + cc.qe1 * G1 + cc.re1 * T1;
            float f20 = C[t][2 * rr]     + cc.qe2 * G0 + cc.re2 * T0;
            float f21 = C[t][2 * rr + 1] + cc.qe2 * G1 + cc.re2 * T1;
            if (i == j0)     { f10 += cc.sf1; f20 += cc.sf2; }
            if (i == j0 + 1) { f11 += cc.sf1; f21 += cc.sf2; }
            split2(f10, f11, Ah[dp][2 * (t & 1) + rr], Al[dp][2 * (t & 1) + rr]);
            uint32_t hw, lw;
            split2(f20, f21, hw, lw);
            *reinterpret_cast<uint32_t*>(smem + SM_F_HI + (i * BSTRIDE + j0) * 2) = hw;
            *reinterpret_cast<uint32_t*>(smem + SM_F_LO + (i * BSTRIDE + j0) * 2) = lw;
        }
    }
    __syncthreads();   // F2 visible

    // ---- M3: C = F1*F2 (balanced tri; F1 != F2 so no diag trick) ----
    mm64_rot(sb, SM_F_HI, SM_F_LO, Ah, Al, lane, w, C, false, npc);

    // ---- final combo + epilogue: p(T) = a8*C + kg12*G + kt13*T + k14*I ----
    // Wrapped tiles (w+dp>=4) hold lower blocks P[16w.., jblk..]; P symmetric ->
    // write their values at transposed triu positions.
    {
        const float SQ2 = 1.41421356237309515f;
        float* ob = out + mat * 2080;
        #pragma unroll
        for (int t = 0; t < 8; ++t) {
            const int dp = t >> 1;
            if (dp >= npc) continue;               // tile not computed
            const bool wrap = (w + dp) >= 4;
            const int j0 = 16 * ((w + dp) & 3) + 8 * (t & 1) + jb;
            #pragma unroll
            for (int rr = 0; rr < 2; ++rr) {
                const int i = ib + 8 * rr;
                const uint32_t th = SMW(SM_T_HI, i, j0), tl = SMW(SM_T_LO, i, j0);
                const uint32_t gh = SMW(SM_G_HI, i, j0), gl = SMW(SM_G_LO, i, j0);
                float f0 = cc.a8 * C[t][2 * rr]     + cc.kg12 * (loW(gh) + loW(gl))
                         + cc.kt13 * (loW(th) + loW(tl));
                float f1 = cc.a8 * C[t][2 * rr + 1] + cc.kg12 * (hiW(gh) + hiW(gl))
                         + cc.kt13 * (hiW(th) + hiW(tl));
                if (!wrap) {
                    if (i == j0)     f0 += cc.k14;
                    if (i == j0 + 1) f1 += cc.k14;
                    const int rowbase = i * (129 - i) / 2 - i;
                    if (j0 >= i)     ob[rowbase + j0]     = (i == j0)     ? fabsf(f0) : fabsf(f0) * SQ2;
                    if (j0 + 1 >= i) ob[rowbase + j0 + 1] = (i == j0 + 1) ? fabsf(f1) : fabsf(f1) * SQ2;
                } else {
                    // i in upper warp rows, j0 < i always; write at (j, i), all off-diag
                    const int ja = j0, jbn = j0 + 1;
                    ob[ja  * (129 - ja)  / 2 - ja  + i] = fabsf(f0) * SQ2;
                    ob[jbn * (129 - jbn) / 2 - jbn + i] = fabsf(f1) * SQ2;
                }
            }
        }
    }
}

extern "C" void kernel_launch(void* const* d_in, const int* in_sizes, int n_in,
                              void* d_out, int out_size)
{
    const float* in = (const float*)d_in[0];
    float* out = (float*)d_out;
    const int nmat = in_sizes[0] / 4096;

    // Chebyshev series of log on [a,b], truncated at degree 8 -> monomials in t.
    const double a = 0.97, b = 7.0;
    const double mm = 0.5 * (a + b);
    const double wdl = (b - a) / (b + a);
    const double z = (sqrt(1.0 - wdl * wdl) - 1.0) / wdl;

    const int ND = 8;
    double c[ND + 1];
    c[0] = log(mm) - log(1.0 + z * z);
    double zk = 1.0;
    for (int k = 1; k <= ND; ++k) { zk *= z; c[k] = -2.0 * zk / (double)k; }

    double am[ND + 1];
    for (int j = 0; j <= ND; ++j) am[j] = 0.0;
    {
        double Tm1[ND + 1] = {0}, Tk[ND + 1] = {0}, Tn[ND + 1];
        Tm1[0] = 1.0;
        Tk[1] = 1.0;
        am[0] += c[0] * Tm1[0];
        am[1] += c[1] * Tk[1];
        for (int k = 2; k <= ND; ++k) {
            for (int j = 0; j <= ND; ++j) Tn[j] = -Tm1[j];
            for (int j = 1; j <= ND; ++j) Tn[j] += 2.0 * Tk[j - 1];
            for (int j = 0; j <= ND; ++j) { am[j] += c[k] * Tn[j]; Tm1[j] = Tk[j]; Tk[j] = Tn[j]; }
        }
    }

    // 3-product scheme coefficients (closed form).
    const double a8 = am[8];
    double bb[8];
    for (int k = 0; k < 8; ++k) bb[k] = am[k] / a8;

    const double p  = bb[7] / 2.0;
    const double Q  = bb[6] - p * p;
    const double R  = bb[5] - p * Q;
    const double dq = 1.0;
    const double S  = bb[4] - p * R - Q * Q / 4.0 + dq * dq;
    const double dr = (p * S + Q * R / 2.0 - bb[3]) / (2.0 * dq);
    const double q1 = Q / 2.0 + dq, q2 = Q / 2.0 - dq;
    const double r1 = R / 2.0 + dr, r2 = R / 2.0 - dr;
    const double s1 = S / 2.0,      s2 = S / 2.0;
    const double c12 = bb[2] - Q * S / 2.0 - R * R / 4.0 + dr * dr;
    const double c13 = bb[1] - R * S / 2.0;
    const double c14 = bb[0] - S * S / 4.0;

    // Square-form refactor: G = y0 + (p/2)T; V = G^2 - (p^2/4)y0; y0 = G - (p/2)T.
    const double hp  = p / 2.0;
    const double qe1 = q1 - p * p / 4.0;
    const double qe2 = q2 - p * p / 4.0;
    const double re1 = r1 - hp * qe1;
    const double re2 = r2 - hp * qe2;
    const double kg12 = a8 * c12;
    const double kt13 = a8 * c13 - hp * kg12;

    Coeffs cc;
    cc.s1 = (float)(2.0 / (b - a));
    cc.s0 = (float)(-(a + b) / (b - a));
    cc.hp = (float)hp;
    cc.qe1 = (float)qe1; cc.re1 = (float)re1; cc.sf1 = (float)s1;
    cc.qe2 = (float)qe2; cc.re2 = (float)re2; cc.sf2 = (float)s2;
    cc.a8 = (float)a8;
    cc.kg12 = (float)kg12;
    cc.kt13 = (float)kt13;
    cc.k14  = (float)(a8 * c14);

    cudaFuncSetAttribute(logeig_s8b_kernel,
                         cudaFuncAttributeMaxDynamicSharedMemorySize, SMEM_BYTES);
    logeig_s8b_kernel<<<nmat, 128, SMEM_BYTES>>>(in, out, cc);
}